// round 15
// baseline (speedup 1.0000x reference)
#include <cuda_runtime.h>
#include <cstdint>

#define N_POINTS  131072
#define N_CENTERS 1024
#define DIM       128
#define BM        64
#define NC        64
#define NCHUNK    16
#define NTHREADS  256

// ---- smem byte offsets ---- (int8 tiles: 64 rows x 128B)
#define SM_XH   0
#define SM_XL   8192
#define SM_CB   16384            // CH(8K)+CL(8K) per buf ; + buf*16384
#define SM_C2   49152            // + buf*256
#define SM_RED  49664            // 64 rows * 4 wc * 32B = 8192
#define SMEM_TOTAL 57856

// swizzled byte offset inside a [rows x 128B] int8 tile
#define SWZ(r, b) ((uint32_t)((r) * 128 + ((b) ^ (((r) & 7) << 4))))

// ---- device scratch ----
__device__ __align__(16) int8_t g_ch[N_CENTERS * DIM];
__device__ __align__(16) int8_t g_cl[N_CENTERS * DIM];
__device__ float g_c2[N_CENTERS];

// =============================== PTX helpers ===============================
__device__ __forceinline__ uint32_t smem_u32(const void* p) {
    uint32_t a;
    asm("{ .reg .u64 t; cvta.to.shared.u64 t, %1; cvt.u32.u64 %0, t; }" : "=r"(a) : "l"(p));
    return a;
}
__device__ __forceinline__ void ldsm4(uint32_t& r0, uint32_t& r1, uint32_t& r2, uint32_t& r3,
                                      uint32_t addr) {
    asm volatile("ldmatrix.sync.aligned.m8n8.x4.shared.b16 {%0,%1,%2,%3}, [%4];"
                 : "=r"(r0), "=r"(r1), "=r"(r2), "=r"(r3) : "r"(addr));
}
__device__ __forceinline__ void imma16832(int* c, const uint32_t* a, uint32_t b0, uint32_t b1) {
    asm volatile("mma.sync.aligned.m16n8k32.row.col.s32.s8.s8.s32 "
                 "{%0,%1,%2,%3}, {%4,%5,%6,%7}, {%8,%9}, {%0,%1,%2,%3};"
                 : "+r"(c[0]), "+r"(c[1]), "+r"(c[2]), "+r"(c[3])
                 : "r"(a[0]), "r"(a[1]), "r"(a[2]), "r"(a[3]), "r"(b0), "r"(b1));
}
#define CP16(s, g) asm volatile("cp.async.cg.shared.global [%0], [%1], 16;" :: "r"(s), "l"(g))
#define CP4(s, g)  asm volatile("cp.async.ca.shared.global [%0], [%1], 4;"  :: "r"(s), "l"(g))
#define CPCOMMIT() asm volatile("cp.async.commit_group;" ::: "memory")
#define CPWAIT1()  asm volatile("cp.async.wait_group 1;" ::: "memory")

// fast int->float, valid |v| < 2^22 (our accs bounded by 4.16e6 worst-case)
__device__ __forceinline__ float i2f(int v) {
    return __int_as_float(0x4B400000 + v) - 12582912.0f;
}
__device__ __forceinline__ void quant8(float f, int& h, int& l) {
    int q = __float2int_rn(f * 4096.0f);
    q = max(-32640, min(32639, q));
    h = (q + 128) >> 8;          // arithmetic, h in [-127,127]
    l = q - (h << 8);            // l in [-128,127]
}
__device__ __forceinline__ uint32_t pack4(int b0, int b1, int b2, int b3) {
    return (uint32_t)(b0 & 0xff) | ((uint32_t)(b1 & 0xff) << 8) |
           ((uint32_t)(b2 & 0xff) << 16) | ((uint32_t)(b3 & 0xff) << 24);
}
__device__ __forceinline__ bool better(float av, int ai, float bv, int bi) {
    return av < bv || (av == bv && ai < bi);
}
__device__ __forceinline__ void upd3(float sc, int col,
                                     float& v0, int& i0, float& v1, int& i1,
                                     float& v2, int& i2) {
    if (sc < v0)      { v2 = v1; i2 = i1; v1 = v0; i1 = i0; v0 = sc; i0 = col; }
    else if (sc < v1) { v2 = v1; i2 = i1; v1 = sc; i1 = col; }
    else if (sc < v2) { v2 = sc; i2 = col; }
}
__device__ __forceinline__ void ins3(float v, int i,
                                     float& v0, int& i0, float& v1, int& i1,
                                     float& v2, int& i2) {
    if (better(v, i, v0, i0))      { v2 = v1; i2 = i1; v1 = v0; i1 = i0; v0 = v; i0 = i; }
    else if (better(v, i, v1, i1)) { v2 = v1; i2 = i1; v1 = v; i1 = i; }
    else if (better(v, i, v2, i2)) { v2 = v; i2 = i; }
}

// ======================= prologue: centers -> int8 hi/lo + c2 =======================
__global__ void prep_centers(const float* __restrict__ c) {
    int row = (blockIdx.x * blockDim.x + threadIdx.x) >> 5;
    int lane = threadIdx.x & 31;
    if (row >= N_CENTERS) return;
    float4 v = reinterpret_cast<const float4*>(c + (size_t)row * DIM)[lane];
    float s = v.x * v.x + v.y * v.y + v.z * v.z + v.w * v.w;
    int h0,l0,h1,l1,h2,l2,h3,l3;
    quant8(v.x,h0,l0); quant8(v.y,h1,l1); quant8(v.z,h2,l2); quant8(v.w,h3,l3);
    reinterpret_cast<uint32_t*>(g_ch + (size_t)row * DIM)[lane] = pack4(h0,h1,h2,h3);
    reinterpret_cast<uint32_t*>(g_cl + (size_t)row * DIM)[lane] = pack4(l0,l1,l2,l3);
    #pragma unroll
    for (int o = 16; o; o >>= 1) s += __shfl_xor_sync(0xffffffffu, s, o);
    if (lane == 0) g_c2[row] = s;
}

// =============================== main kernel ===============================
__global__ __launch_bounds__(NTHREADS, 2)
void kmeans_imma_kernel(const float* __restrict__ x, const float* __restrict__ cen,
                        float* __restrict__ out, int write_idx) {
    extern __shared__ char smem[];
    const uint32_t sbase = smem_u32(smem);
    const int tid  = threadIdx.x;
    const int warp = tid >> 5;
    const int lane = tid & 31;
    const int wr = warp & 1;      // rows wr*32 .. +32
    const int wc = warp >> 1;     // cols wc*16 .. +16
    const int sub = lane >> 3;
    const int i8  = lane & 7;
    const int row0 = blockIdx.x * BM;

    // ---- stage x rows into XH/XL (int8 hi/lo, swizzled 128B rows) ----
    {
        int r = tid >> 2, h = tid & 3;   // elems [h*32, h*32+32)
        const float4* src = reinterpret_cast<const float4*>(
            x + (size_t)(row0 + r) * DIM + h * 32);
        uint32_t hw[8], lw[8];
        #pragma unroll
        for (int j = 0; j < 8; j++) {
            float4 v = src[j];
            int h0,l0,h1,l1,h2,l2,h3,l3;
            quant8(v.x,h0,l0); quant8(v.y,h1,l1); quant8(v.z,h2,l2); quant8(v.w,h3,l3);
            hw[j] = pack4(h0,h1,h2,h3);
            lw[j] = pack4(l0,l1,l2,l3);
        }
        uint32_t o0 = SWZ(r, h * 32), o1 = SWZ(r, h * 32 + 16);
        *reinterpret_cast<uint4*>(smem + SM_XH + o0) = make_uint4(hw[0],hw[1],hw[2],hw[3]);
        *reinterpret_cast<uint4*>(smem + SM_XH + o1) = make_uint4(hw[4],hw[5],hw[6],hw[7]);
        *reinterpret_cast<uint4*>(smem + SM_XL + o0) = make_uint4(lw[0],lw[1],lw[2],lw[3]);
        *reinterpret_cast<uint4*>(smem + SM_XL + o1) = make_uint4(lw[4],lw[5],lw[6],lw[7]);
    }

    // ---- cp.async loader for a center chunk (CH + CL int8, 64 centers) ----
    auto load_chunk = [&](int chunk, int buf) {
        const int8_t* gh = g_ch + (size_t)chunk * NC * DIM;
        const int8_t* gl = g_cl + (size_t)chunk * NC * DIM;
        uint32_t dh = sbase + SM_CB + buf * 16384;
        uint32_t dl = dh + 8192;
        #pragma unroll
        for (int it = 0; it < 2; it++) {
            int v = tid + it * NTHREADS;       // 512 16B-units per 8KB tile
            int r = v >> 3, c16 = v & 7;
            uint32_t so = SWZ(r, c16 * 16);
            CP16(dh + so, gh + r * DIM + c16 * 16);
            CP16(dl + so, gl + r * DIM + c16 * 16);
        }
        if (tid < NC)
            CP4(sbase + SM_C2 + buf * 256 + tid * 4, g_c2 + chunk * NC + tid);
    };

    load_chunk(0, 0);
    CPCOMMIT();
    __syncthreads();   // x tiles visible

    // per-thread ldmatrix address components (int8: 128B rows, 32B per k-step)
    const int aRow = wr * 32 + ((sub & 1) << 3) + i8;
    const int bRow = wc * 16 + ((sub >> 1) << 3) + i8;
    const uint32_t aBase = (uint32_t)aRow * 128;
    const uint32_t bBase = (uint32_t)bRow * 128;
    const uint32_t aKb   = (uint32_t)((sub >> 1) << 4);
    const uint32_t bKb   = (uint32_t)((sub & 1) << 4);
    const uint32_t aXor  = (uint32_t)((aRow & 7) << 4);
    const uint32_t bXor  = (uint32_t)((bRow & 7) << 4);

    // top-3 state: 4 rows per thread
    float v0[4], v1[4], v2[4];
    int   i0[4], i1[4], i2[4];
    #pragma unroll
    for (int r = 0; r < 4; r++) {
        v0[r] = v1[r] = v2[r] = 3.402823e38f;
        i0[r] = i1[r] = i2[r] = 0x7fffffff;
    }

    #pragma unroll 1
    for (int ci = 0; ci < NCHUNK; ci++) {
        const int buf = ci & 1;
        if (ci + 1 < NCHUNK) load_chunk(ci + 1, (ci + 1) & 1);
        CPCOMMIT();
        CPWAIT1();
        __syncthreads();   // chunk ci visible

        int ahh[2][2][4], amid[2][2][4], all_[2][2][4];
        #pragma unroll
        for (int mt = 0; mt < 2; mt++)
            #pragma unroll
            for (int nt = 0; nt < 2; nt++)
                #pragma unroll
                for (int q = 0; q < 4; q++) {
                    ahh[mt][nt][q] = 0; amid[mt][nt][q] = 0; all_[mt][nt][q] = 0;
                }

        const uint32_t chB = sbase + SM_CB + buf * 16384;
        const uint32_t clB = chB + 8192;
        #pragma unroll
        for (int ks = 0; ks < 4; ks++) {
            const uint32_t akb = (ks * 32 + aKb) ^ aXor;
            const uint32_t bkb = (ks * 32 + bKb) ^ bXor;
            uint32_t ah[8], al[8], bh[4], bl[4];
            ldsm4(ah[0], ah[1], ah[2], ah[3], sbase + SM_XH + aBase + akb);
            ldsm4(ah[4], ah[5], ah[6], ah[7], sbase + SM_XH + aBase + 16 * 128 + akb);
            ldsm4(al[0], al[1], al[2], al[3], sbase + SM_XL + aBase + akb);
            ldsm4(al[4], al[5], al[6], al[7], sbase + SM_XL + aBase + 16 * 128 + akb);
            ldsm4(bh[0], bh[1], bh[2], bh[3], chB + bBase + bkb);
            ldsm4(bl[0], bl[1], bl[2], bl[3], clB + bBase + bkb);
            #pragma unroll
            for (int mt = 0; mt < 2; mt++)
                #pragma unroll
                for (int nt = 0; nt < 2; nt++) {
                    imma16832(ahh[mt][nt],  &ah[mt*4], bh[nt*2], bh[nt*2 + 1]);
                    imma16832(amid[mt][nt], &ah[mt*4], bl[nt*2], bl[nt*2 + 1]);
                    imma16832(amid[mt][nt], &al[mt*4], bh[nt*2], bh[nt*2 + 1]);
                    imma16832(all_[mt][nt], &al[mt*4], bl[nt*2], bl[nt*2 + 1]);
                }
        }

        // epilogue: dot_fixed = 65536*hh + 256*mid + ll (exact 16-bit fixed point)
        // score = c2 - 2*dot = c2 - hh/128 - mid/32768 - ll/8388608
        const float* c2s = reinterpret_cast<const float*>(smem + SM_C2 + buf * 256);
        float2 c2r[2];
        #pragma unroll
        for (int nt = 0; nt < 2; nt++)
            c2r[nt] = *reinterpret_cast<const float2*>(&c2s[wc * 16 + nt * 8 + 2 * (lane & 3)]);
        const int colBase = ci * NC + wc * 16 + 2 * (lane & 3);
        #pragma unroll
        for (int nt = 0; nt < 2; nt++) {
            const int col = colBase + nt * 8;
            #pragma unroll
            for (int mt = 0; mt < 2; mt++) {
                #pragma unroll
                for (int q = 0; q < 4; q++) {
                    float sc = c2r[nt].x;
                    if (q & 1) sc = c2r[nt].y;
                    sc = fmaf(-7.8125e-3f,      i2f(ahh[mt][nt][q]),  sc);   // 1/128
                    sc = fmaf(-3.0517578e-5f,   i2f(amid[mt][nt][q]), sc);   // 1/32768
                    sc = fmaf(-1.1920929e-7f,   i2f(all_[mt][nt][q]), sc);   // 1/8388608
                    const int rid = mt * 2 + (q >> 1);
                    upd3(sc, col + (q & 1), v0[rid], i0[rid], v1[rid], i1[rid], v2[rid], i2[rid]);
                }
            }
        }
        __syncthreads();   // done reading buffer before next prefetch overwrites it
    }

    // ---- quad butterfly (lanes sharing the same rows), merging top-3 lists ----
    #pragma unroll
    for (int m = 1; m <= 2; m <<= 1) {
        #pragma unroll
        for (int rid = 0; rid < 4; rid++) {
            float ov0 = __shfl_xor_sync(0xffffffffu, v0[rid], m);
            int   oi0 = __shfl_xor_sync(0xffffffffu, i0[rid], m);
            float ov1 = __shfl_xor_sync(0xffffffffu, v1[rid], m);
            int   oi1 = __shfl_xor_sync(0xffffffffu, i1[rid], m);
            float ov2 = __shfl_xor_sync(0xffffffffu, v2[rid], m);
            int   oi2 = __shfl_xor_sync(0xffffffffu, i2[rid], m);
            ins3(ov0, oi0, v0[rid], i0[rid], v1[rid], i1[rid], v2[rid], i2[rid]);
            ins3(ov1, oi1, v0[rid], i0[rid], v1[rid], i1[rid], v2[rid], i2[rid]);
            ins3(ov2, oi2, v0[rid], i0[rid], v1[rid], i1[rid], v2[rid], i2[rid]);
        }
    }
    if ((lane & 3) == 0) {
        #pragma unroll
        for (int rid = 0; rid < 4; rid++) {
            int rl = wr * 32 + (rid >> 1) * 16 + (lane >> 2) + (rid & 1) * 8;
            char* dst = smem + SM_RED + (rl * 4 + wc) * 32;
            *reinterpret_cast<float4*>(dst) =
                make_float4(v0[rid], __int_as_float(i0[rid]), v1[rid], __int_as_float(i1[rid]));
            *reinterpret_cast<float2*>(dst + 16) =
                make_float2(v2[rid], __int_as_float(i2[rid]));
        }
    }
    __syncthreads();

    // ---- final merge (4 col-warps) + exact fp32 top-3 refine ----
    if (tid < BM) {
        float fv0 = 3.402823e38f, fv1 = 3.402823e38f, fv2 = 3.402823e38f;
        int   fi0 = 0x7fffffff,   fi1 = 0x7fffffff,   fi2 = 0x7fffffff;
        #pragma unroll
        for (int wcc = 0; wcc < 4; wcc++) {
            const char* src = smem + SM_RED + (tid * 4 + wcc) * 32;
            float4 e  = *reinterpret_cast<const float4*>(src);
            float2 e2 = *reinterpret_cast<const float2*>(src + 16);
            ins3(e.x,  __float_as_int(e.y),  fv0, fi0, fv1, fi1, fv2, fi2);
            ins3(e.z,  __float_as_int(e.w),  fv0, fi0, fv1, fi1, fv2, fi2);
            ins3(e2.x, __float_as_int(e2.y), fv0, fi0, fv1, fi1, fv2, fi2);
        }

        const int row = row0 + tid;
        const float4* xr  = reinterpret_cast<const float4*>(x   + (size_t)row * DIM);
        const float4* cp0 = reinterpret_cast<const float4*>(cen + (size_t)fi0 * DIM);
        const float4* cp1 = reinterpret_cast<const float4*>(cen + (size_t)fi1 * DIM);
        const float4* cp2 = reinterpret_cast<const float4*>(cen + (size_t)fi2 * DIM);
        float x2 = 0.f, d0 = 0.f, d1 = 0.f, d2 = 0.f;
        #pragma unroll
        for (int k = 0; k < 32; k++) {
            float4 xv = xr[k], a = cp0[k], b = cp1[k], cc = cp2[k];
            x2 = fmaf(xv.x, xv.x, x2); x2 = fmaf(xv.y, xv.y, x2);
            x2 = fmaf(xv.z, xv.z, x2); x2 = fmaf(xv.w, xv.w, x2);
            d0 = fmaf(xv.x, a.x, d0);  d0 = fmaf(xv.y, a.y, d0);
            d0 = fmaf(xv.z, a.z, d0);  d0 = fmaf(xv.w, a.w, d0);
            d1 = fmaf(xv.x, b.x, d1);  d1 = fmaf(xv.y, b.y, d1);
            d1 = fmaf(xv.z, b.z, d1);  d1 = fmaf(xv.w, b.w, d1);
            d2 = fmaf(xv.x, cc.x, d2); d2 = fmaf(xv.y, cc.y, d2);
            d2 = fmaf(xv.z, cc.z, d2); d2 = fmaf(xv.w, cc.w, d2);
        }
        float dist0 = fmaf(-2.f, d0, x2 + g_c2[fi0]);
        float dist1 = fmaf(-2.f, d1, x2 + g_c2[fi1]);
        float dist2 = fmaf(-2.f, d2, x2 + g_c2[fi2]);
        float cost = dist0; int widx = fi0;
        if (better(dist1, fi1, cost, widx)) { cost = dist1; widx = fi1; }
        if (better(dist2, fi2, cost, widx)) { cost = dist2; widx = fi2; }
        out[row] = cost > 0.f ? cost : 0.f;
        if (write_idx) out[N_POINTS + row] = (float)widx;
    }
}

// =============================== launch ===============================
extern "C" void kernel_launch(void* const* d_in, const int* in_sizes, int n_in,
                              void* d_out, int out_size) {
    const float* x = (const float*)d_in[0];   // [131072, 128]
    const float* c = (const float*)d_in[1];   // [1024, 128]
    float* out = (float*)d_out;

    prep_centers<<<N_CENTERS / 8, 256>>>(c);

    cudaFuncSetAttribute(kmeans_imma_kernel,
                         cudaFuncAttributeMaxDynamicSharedMemorySize, SMEM_TOTAL);
    int write_idx = (out_size >= 2 * N_POINTS) ? 1 : 0;
    kmeans_imma_kernel<<<N_POINTS / BM, NTHREADS, SMEM_TOTAL>>>(x, c, out, write_idx);
}

// round 16
// speedup vs baseline: 1.8511x; 1.8511x over previous
#include <cuda_runtime.h>
#include <cuda_bf16.h>
#include <cstdint>

#define N_POINTS  131072
#define N_CENTERS 1024
#define DIM       128
#define BM        64
#define NC        64
#define NCHUNK    16
#define NTHREADS  256
#define EPS       0.6f

// ---- smem byte offsets (dynamic smem) ----
#define SM_XH   0                 // 64 rows * 256B = 16384
#define SM_XL   16384
#define SM_CB   32768             // CH only, 16KB per buf ; + buf*16384
#define SM_C2   65536             // + buf*256
#define SM_RED  66048             // 64 rows * 4 wc * 32B = 8192
#define SM_FLG  74240             // 64 ints
#define SM_XROW 74496             // 512B staged x row (fallback)
#define SM_KEY  75008             // 8B packed argmin key
#define SMEM_TOTAL 75776

// swizzled byte offset inside a [rows x 256B] bf16 tile
#define SWZ(r, kb) ((uint32_t)((r) * 256 + ((kb) ^ (((r) & 7) << 4))))

// ---- device scratch (no cudaMalloc allowed) ----
__device__ __align__(16) __nv_bfloat16 g_ch[N_CENTERS * DIM];
__device__ float g_c2[N_CENTERS];

// =============================== PTX helpers ===============================
__device__ __forceinline__ uint32_t smem_u32(const void* p) {
    uint32_t a;
    asm("{ .reg .u64 t; cvta.to.shared.u64 t, %1; cvt.u32.u64 %0, t; }" : "=r"(a) : "l"(p));
    return a;
}
__device__ __forceinline__ void ldsm4(uint32_t& r0, uint32_t& r1, uint32_t& r2, uint32_t& r3,
                                      uint32_t addr) {
    asm volatile("ldmatrix.sync.aligned.m8n8.x4.shared.b16 {%0,%1,%2,%3}, [%4];"
                 : "=r"(r0), "=r"(r1), "=r"(r2), "=r"(r3) : "r"(addr));
}
__device__ __forceinline__ void mma16816(float* c, const uint32_t* a, uint32_t b0, uint32_t b1) {
    asm volatile("mma.sync.aligned.m16n8k16.row.col.f32.bf16.bf16.f32 "
                 "{%0,%1,%2,%3}, {%4,%5,%6,%7}, {%8,%9}, {%0,%1,%2,%3};"
                 : "+f"(c[0]), "+f"(c[1]), "+f"(c[2]), "+f"(c[3])
                 : "r"(a[0]), "r"(a[1]), "r"(a[2]), "r"(a[3]), "r"(b0), "r"(b1));
}
#define CP16(s, g) asm volatile("cp.async.cg.shared.global [%0], [%1], 16;" :: "r"(s), "l"(g))
#define CP4(s, g)  asm volatile("cp.async.ca.shared.global [%0], [%1], 4;"  :: "r"(s), "l"(g))
#define CPCOMMIT() asm volatile("cp.async.commit_group;" ::: "memory")
#define CPWAIT1()  asm volatile("cp.async.wait_group 1;" ::: "memory")

__device__ __forceinline__ uint32_t pack_bf16(float a, float b) {
    __nv_bfloat162 h = __floats2bfloat162_rn(a, b);
    return *reinterpret_cast<uint32_t*>(&h);
}
__device__ __forceinline__ void split2(float f, float& h, float& l) {
    __nv_bfloat16 hb = __float2bfloat16_rn(f);
    h = __bfloat162float(hb);
    l = f - h;
}
__device__ __forceinline__ bool better(float av, int ai, float bv, int bi) {
    return av < bv || (av == bv && ai < bi);
}
__device__ __forceinline__ void upd3(float sc, int col,
                                     float& v0, int& i0, float& v1, int& i1,
                                     float& v2, int& i2) {
    if (sc < v0)      { v2 = v1; i2 = i1; v1 = v0; i1 = i0; v0 = sc; i0 = col; }
    else if (sc < v1) { v2 = v1; i2 = i1; v1 = sc; i1 = col; }
    else if (sc < v2) { v2 = sc; i2 = col; }
}
__device__ __forceinline__ void ins3(float v, int i,
                                     float& v0, int& i0, float& v1, int& i1,
                                     float& v2, int& i2) {
    if (better(v, i, v0, i0))      { v2 = v1; i2 = i1; v1 = v0; i1 = i0; v0 = v; i0 = i; }
    else if (better(v, i, v1, i1)) { v2 = v1; i2 = i1; v1 = v; i1 = i; }
    else if (better(v, i, v2, i2)) { v2 = v; i2 = i; }
}
// monotone float -> uint map (handles negatives)
__device__ __forceinline__ uint32_t ford(float f) {
    uint32_t b = __float_as_uint(f);
    return b ^ (uint32_t)(((int32_t)b >> 31) | 0x80000000);
}

// ======================= prologue: centers -> bf16 + c2 =======================
__global__ void prep_centers(const float* __restrict__ c) {
    int row = (blockIdx.x * blockDim.x + threadIdx.x) >> 5;
    int lane = threadIdx.x & 31;
    if (row >= N_CENTERS) return;
    float4 v = reinterpret_cast<const float4*>(c + (size_t)row * DIM)[lane];
    float s = v.x * v.x + v.y * v.y + v.z * v.z + v.w * v.w;
    reinterpret_cast<uint2*>(g_ch + (size_t)row * DIM)[lane] =
        make_uint2(pack_bf16(v.x, v.y), pack_bf16(v.z, v.w));
    #pragma unroll
    for (int o = 16; o; o >>= 1) s += __shfl_xor_sync(0xffffffffu, s, o);
    if (lane == 0) g_c2[row] = s;
}

// =============================== main kernel ===============================
__global__ __launch_bounds__(NTHREADS, 2)
void kmeans_hmma_kernel(const float* __restrict__ x, const float* __restrict__ cen,
                        float* __restrict__ out, int write_idx) {
    extern __shared__ char smem[];
    const uint32_t sbase = smem_u32(smem);
    const int tid  = threadIdx.x;
    const int warp = tid >> 5;
    const int lane = tid & 31;
    const int wr = warp & 1;      // rows wr*32 .. +32
    const int wc = warp >> 1;     // cols wc*16 .. +16
    const int sub = lane >> 3;
    const int i8  = lane & 7;
    const int row0 = blockIdx.x * BM;

    // ---- stage x rows into XH/XL (hi/lo bf16, swizzled) ----
    {
        int r = tid >> 2, h = tid & 3;
        const float4* src = reinterpret_cast<const float4*>(
            x + (size_t)(row0 + r) * DIM + h * 32);
        #pragma unroll
        for (int j = 0; j < 4; j++) {
            float4 v0 = src[j * 2], v1 = src[j * 2 + 1];
            float h0,l0,h1,l1,h2,l2,h3,l3,h4,l4,h5,l5,h6,l6,h7,l7;
            split2(v0.x,h0,l0); split2(v0.y,h1,l1); split2(v0.z,h2,l2); split2(v0.w,h3,l3);
            split2(v1.x,h4,l4); split2(v1.y,h5,l5); split2(v1.z,h6,l6); split2(v1.w,h7,l7);
            uint32_t so = SWZ(r, h * 64 + j * 16);
            *reinterpret_cast<uint4*>(smem + SM_XH + so) =
                make_uint4(pack_bf16(h0,h1), pack_bf16(h2,h3), pack_bf16(h4,h5), pack_bf16(h6,h7));
            *reinterpret_cast<uint4*>(smem + SM_XL + so) =
                make_uint4(pack_bf16(l0,l1), pack_bf16(l2,l3), pack_bf16(l4,l5), pack_bf16(l6,l7));
        }
    }

    // ---- cp.async loader for a center chunk (CH only, 64 centers) ----
    auto load_chunk = [&](int chunk, int buf) {
        const __nv_bfloat16* gh = g_ch + (size_t)chunk * NC * DIM;
        uint32_t dh = sbase + SM_CB + buf * 16384;
        #pragma unroll
        for (int it = 0; it < 4; it++) {
            int v = tid + it * NTHREADS;
            int r = v >> 4, c16 = v & 15;
            CP16(dh + SWZ(r, c16 * 16), gh + r * DIM + c16 * 8);
        }
        if (tid < NC)
            CP4(sbase + SM_C2 + buf * 256 + tid * 4, g_c2 + chunk * NC + tid);
    };

    load_chunk(0, 0);
    CPCOMMIT();
    __syncthreads();

    const uint32_t aRowB = (uint32_t)(wr * 32 + ((sub & 1) << 3) + i8) * 256;
    const uint32_t aKb   = (uint32_t)((sub >> 1) << 4);
    const uint32_t bRowB = (uint32_t)(wc * 16 + ((sub >> 1) << 3) + i8) * 256;
    const uint32_t bKb   = (uint32_t)((sub & 1) << 4);
    const uint32_t kXor  = (uint32_t)(i8 << 4);

    float v0[4], v1[4], v2[4];
    int   i0[4], i1[4], i2[4];
    #pragma unroll
    for (int r = 0; r < 4; r++) {
        v0[r] = v1[r] = v2[r] = 3.402823e38f;
        i0[r] = i1[r] = i2[r] = 0x7fffffff;
    }

    #pragma unroll 1
    for (int ci = 0; ci < NCHUNK; ci++) {
        const int buf = ci & 1;
        if (ci + 1 < NCHUNK) load_chunk(ci + 1, (ci + 1) & 1);
        CPCOMMIT();
        CPWAIT1();
        __syncthreads();

        float acc[2][2][4];
        #pragma unroll
        for (int mt = 0; mt < 2; mt++)
            #pragma unroll
            for (int nt = 0; nt < 2; nt++)
                #pragma unroll
                for (int q = 0; q < 4; q++) acc[mt][nt][q] = 0.f;

        const uint32_t chB = sbase + SM_CB + buf * 16384;
        #pragma unroll
        for (int ks = 0; ks < 8; ks++) {
            const uint32_t kb = ks * 32;
            const uint32_t aOff = aRowB + ((kb + aKb) ^ kXor);
            const uint32_t bOff = bRowB + ((kb + bKb) ^ kXor);
            uint32_t ah[8], al[8], bh[4];
            ldsm4(ah[0], ah[1], ah[2], ah[3], sbase + SM_XH + aOff);
            ldsm4(ah[4], ah[5], ah[6], ah[7], sbase + SM_XH + aOff + 16 * 256);
            ldsm4(al[0], al[1], al[2], al[3], sbase + SM_XL + aOff);
            ldsm4(al[4], al[5], al[6], al[7], sbase + SM_XL + aOff + 16 * 256);
            ldsm4(bh[0], bh[1], bh[2], bh[3], chB + bOff);
            // pass 1: XH*CH ; pass 2: XL*CH  ->  (xh+xl)*ch
            #pragma unroll
            for (int mt = 0; mt < 2; mt++)
                #pragma unroll
                for (int nt = 0; nt < 2; nt++)
                    mma16816(acc[mt][nt], &ah[mt*4], bh[nt*2], bh[nt*2 + 1]);
            #pragma unroll
            for (int mt = 0; mt < 2; mt++)
                #pragma unroll
                for (int nt = 0; nt < 2; nt++)
                    mma16816(acc[mt][nt], &al[mt*4], bh[nt*2], bh[nt*2 + 1]);
        }

        const float* c2s = reinterpret_cast<const float*>(smem + SM_C2 + buf * 256);
        float2 c2r[2];
        #pragma unroll
        for (int nt = 0; nt < 2; nt++)
            c2r[nt] = *reinterpret_cast<const float2*>(&c2s[wc * 16 + nt * 8 + 2 * (lane & 3)]);
        const int colBase = ci * NC + wc * 16 + 2 * (lane & 3);
        #pragma unroll
        for (int nt = 0; nt < 2; nt++) {
            const int col = colBase + nt * 8;
            #pragma unroll
            for (int mt = 0; mt < 2; mt++) {
                upd3(fmaf(-2.f, acc[mt][nt][0], c2r[nt].x), col,
                     v0[mt*2],   i0[mt*2],   v1[mt*2],   i1[mt*2],   v2[mt*2],   i2[mt*2]);
                upd3(fmaf(-2.f, acc[mt][nt][1], c2r[nt].y), col + 1,
                     v0[mt*2],   i0[mt*2],   v1[mt*2],   i1[mt*2],   v2[mt*2],   i2[mt*2]);
                upd3(fmaf(-2.f, acc[mt][nt][2], c2r[nt].x), col,
                     v0[mt*2+1], i0[mt*2+1], v1[mt*2+1], i1[mt*2+1], v2[mt*2+1], i2[mt*2+1]);
                upd3(fmaf(-2.f, acc[mt][nt][3], c2r[nt].y), col + 1,
                     v0[mt*2+1], i0[mt*2+1], v1[mt*2+1], i1[mt*2+1], v2[mt*2+1], i2[mt*2+1]);
            }
        }
        __syncthreads();
    }

    // ---- quad butterfly, merging top-3 lists ----
    #pragma unroll
    for (int m = 1; m <= 2; m <<= 1) {
        #pragma unroll
        for (int rid = 0; rid < 4; rid++) {
            float ov0 = __shfl_xor_sync(0xffffffffu, v0[rid], m);
            int   oi0 = __shfl_xor_sync(0xffffffffu, i0[rid], m);
            float ov1 = __shfl_xor_sync(0xffffffffu, v1[rid], m);
            int   oi1 = __shfl_xor_sync(0xffffffffu, i1[rid], m);
            float ov2 = __shfl_xor_sync(0xffffffffu, v2[rid], m);
            int   oi2 = __shfl_xor_sync(0xffffffffu, i2[rid], m);
            ins3(ov0, oi0, v0[rid], i0[rid], v1[rid], i1[rid], v2[rid], i2[rid]);
            ins3(ov1, oi1, v0[rid], i0[rid], v1[rid], i1[rid], v2[rid], i2[rid]);
            ins3(ov2, oi2, v0[rid], i0[rid], v1[rid], i1[rid], v2[rid], i2[rid]);
        }
    }
    if ((lane & 3) == 0) {
        #pragma unroll
        for (int rid = 0; rid < 4; rid++) {
            int rl = wr * 32 + (rid >> 1) * 16 + (lane >> 2) + (rid & 1) * 8;
            char* dst = smem + SM_RED + (rl * 4 + wc) * 32;
            *reinterpret_cast<float4*>(dst) =
                make_float4(v0[rid], __int_as_float(i0[rid]), v1[rid], __int_as_float(i1[rid]));
            *reinterpret_cast<float2*>(dst + 16) =
                make_float2(v2[rid], __int_as_float(i2[rid]));
        }
    }
    __syncthreads();

    // ---- final merge + exact fp32 top-3 refine + escape flag ----
    if (tid < BM) {
        float fv0 = 3.402823e38f, fv1 = 3.402823e38f, fv2 = 3.402823e38f;
        int   fi0 = 0x7fffffff,   fi1 = 0x7fffffff,   fi2 = 0x7fffffff;
        #pragma unroll
        for (int wcc = 0; wcc < 4; wcc++) {
            const char* src = smem + SM_RED + (tid * 4 + wcc) * 32;
            float4 e  = *reinterpret_cast<const float4*>(src);
            float2 e2 = *reinterpret_cast<const float2*>(src + 16);
            ins3(e.x,  __float_as_int(e.y),  fv0, fi0, fv1, fi1, fv2, fi2);
            ins3(e.z,  __float_as_int(e.w),  fv0, fi0, fv1, fi1, fv2, fi2);
            ins3(e2.x, __float_as_int(e2.y), fv0, fi0, fv1, fi1, fv2, fi2);
        }

        // margin certificate: escape from top-3 implies fv2 - fv0 < 2*eps
        reinterpret_cast<int*>(smem + SM_FLG)[tid] = (fv2 - fv0 < EPS) ? 1 : 0;

        const int row = row0 + tid;
        const float4* xr  = reinterpret_cast<const float4*>(x   + (size_t)row * DIM);
        const float4* cp0 = reinterpret_cast<const float4*>(cen + (size_t)fi0 * DIM);
        const float4* cp1 = reinterpret_cast<const float4*>(cen + (size_t)fi1 * DIM);
        const float4* cp2 = reinterpret_cast<const float4*>(cen + (size_t)fi2 * DIM);
        float x2 = 0.f, d0 = 0.f, d1 = 0.f, d2 = 0.f;
        #pragma unroll
        for (int k = 0; k < 32; k++) {
            float4 xv = xr[k], a = cp0[k], b = cp1[k], cc = cp2[k];
            x2 = fmaf(xv.x, xv.x, x2); x2 = fmaf(xv.y, xv.y, x2);
            x2 = fmaf(xv.z, xv.z, x2); x2 = fmaf(xv.w, xv.w, x2);
            d0 = fmaf(xv.x, a.x, d0);  d0 = fmaf(xv.y, a.y, d0);
            d0 = fmaf(xv.z, a.z, d0);  d0 = fmaf(xv.w, a.w, d0);
            d1 = fmaf(xv.x, b.x, d1);  d1 = fmaf(xv.y, b.y, d1);
            d1 = fmaf(xv.z, b.z, d1);  d1 = fmaf(xv.w, b.w, d1);
            d2 = fmaf(xv.x, cc.x, d2); d2 = fmaf(xv.y, cc.y, d2);
            d2 = fmaf(xv.z, cc.z, d2); d2 = fmaf(xv.w, cc.w, d2);
        }
        float dist0 = fmaf(-2.f, d0, x2 + g_c2[fi0]);
        float dist1 = fmaf(-2.f, d1, x2 + g_c2[fi1]);
        float dist2 = fmaf(-2.f, d2, x2 + g_c2[fi2]);
        float cost = dist0; int widx = fi0;
        if (better(dist1, fi1, cost, widx)) { cost = dist1; widx = fi1; }
        if (better(dist2, fi2, cost, widx)) { cost = dist2; widx = fi2; }
        out[row] = cost > 0.f ? cost : 0.f;
        if (write_idx) out[N_POINTS + row] = (float)widx;
    }
    __syncthreads();

    // ---- exact fallback for flagged rows (rare): full 1024-center fp32 scan ----
    #pragma unroll 1
    for (int r = 0; r < BM; r++) {
        if (reinterpret_cast<int*>(smem + SM_FLG)[r]) {
            if (tid < 32)
                reinterpret_cast<float4*>(smem + SM_XROW)[tid] =
                    reinterpret_cast<const float4*>(x + (size_t)(row0 + r) * DIM)[tid];
            if (tid == 0)
                *reinterpret_cast<unsigned long long*>(smem + SM_KEY) = ~0ull;
            __syncthreads();
            const float4* xs = reinterpret_cast<const float4*>(smem + SM_XROW);
            unsigned long long bk = ~0ull;
            #pragma unroll 1
            for (int k = 0; k < 4; k++) {
                int cid = tid + k * NTHREADS;
                const float4* cr = reinterpret_cast<const float4*>(cen + (size_t)cid * DIM);
                float dot = 0.f;
                #pragma unroll
                for (int j = 0; j < 32; j++) {
                    float4 xv = xs[j], cv = cr[j];
                    dot = fmaf(xv.x, cv.x, dot); dot = fmaf(xv.y, cv.y, dot);
                    dot = fmaf(xv.z, cv.z, dot); dot = fmaf(xv.w, cv.w, dot);
                }
                float sc = fmaf(-2.f, dot, g_c2[cid]);
                unsigned long long key =
                    ((unsigned long long)ford(sc) << 32) | (unsigned)cid;
                if (key < bk) bk = key;
            }
            atomicMin(reinterpret_cast<unsigned long long*>(smem + SM_KEY), bk);
            __syncthreads();
            if (tid == 0) {
                int wcid = (int)(*reinterpret_cast<unsigned long long*>(smem + SM_KEY)
                                 & 0xFFFFFFFFull);
                const float4* xg = reinterpret_cast<const float4*>(x + (size_t)(row0 + r) * DIM);
                const float4* cr = reinterpret_cast<const float4*>(cen + (size_t)wcid * DIM);
                float x2 = 0.f, dot = 0.f;
                #pragma unroll
                for (int j = 0; j < 32; j++) {
                    float4 xv = xg[j], cv = cr[j];
                    x2  = fmaf(xv.x, xv.x, x2);  x2  = fmaf(xv.y, xv.y, x2);
                    x2  = fmaf(xv.z, xv.z, x2);  x2  = fmaf(xv.w, xv.w, x2);
                    dot = fmaf(xv.x, cv.x, dot); dot = fmaf(xv.y, cv.y, dot);
                    dot = fmaf(xv.z, cv.z, dot); dot = fmaf(xv.w, cv.w, dot);
                }
                float cost = fmaf(-2.f, dot, x2 + g_c2[wcid]);
                out[row0 + r] = cost > 0.f ? cost : 0.f;
                if (write_idx) out[N_POINTS + row0 + r] = (float)wcid;
            }
            __syncthreads();
        }
    }
}

// =============================== launch ===============================
extern "C" void kernel_launch(void* const* d_in, const int* in_sizes, int n_in,
                              void* d_out, int out_size) {
    const float* x = (const float*)d_in[0];   // [131072, 128]
    const float* c = (const float*)d_in[1];   // [1024, 128]
    float* out = (float*)d_out;

    prep_centers<<<N_CENTERS / 8, 256>>>(c);

    cudaFuncSetAttribute(kmeans_hmma_kernel,
                         cudaFuncAttributeMaxDynamicSharedMemorySize, SMEM_TOTAL);
    int write_idx = (out_size >= 2 * N_POINTS) ? 1 : 0;
    kmeans_hmma_kernel<<<N_POINTS / BM, NTHREADS, SMEM_TOTAL>>>(x, c, out, write_idx);
}

// round 17
// speedup vs baseline: 1.9782x; 1.0687x over previous
#include <cuda_runtime.h>
#include <cuda_bf16.h>
#include <cstdint>

#define N_POINTS  131072
#define N_CENTERS 1024
#define DIM       128
#define BM        64
#define NC        64
#define NCHUNK    16
#define NTHREADS  256

// ---- smem byte offsets (dynamic smem) ----
#define SM_XH   0                 // 64 rows * 256B = 16384
#define SM_XL   16384
#define SM_CH   32768             // single-buffered, 16KB
#define SM_CL   49152             // single-buffered, 16KB
#define SM_C2   65536             // + buf*256 (double-buffered, 512B)
#define SM_RED  66560             // 64 rows * 4 wc * 16B = 4096
#define SMEM_TOTAL 70656

// swizzled byte offset inside a [rows x 256B] tile
#define SWZ(r, kb) ((uint32_t)((r) * 256 + ((kb) ^ (((r) & 7) << 4))))

// ---- device scratch (no cudaMalloc allowed) ----
__device__ __align__(16) __nv_bfloat16 g_ch[N_CENTERS * DIM];
__device__ __align__(16) __nv_bfloat16 g_cl[N_CENTERS * DIM];
__device__ float g_c2[N_CENTERS];

// =============================== PTX helpers (target-agnostic sm_80 set) ===========
__device__ __forceinline__ uint32_t smem_u32(const void* p) {
    uint32_t a;
    asm("{ .reg .u64 t; cvta.to.shared.u64 t, %1; cvt.u32.u64 %0, t; }" : "=r"(a) : "l"(p));
    return a;
}
__device__ __forceinline__ void ldsm4(uint32_t& r0, uint32_t& r1, uint32_t& r2, uint32_t& r3,
                                      uint32_t addr) {
    asm volatile("ldmatrix.sync.aligned.m8n8.x4.shared.b16 {%0,%1,%2,%3}, [%4];"
                 : "=r"(r0), "=r"(r1), "=r"(r2), "=r"(r3) : "r"(addr));
}
__device__ __forceinline__ void mma16816(float* c, const uint32_t* a, uint32_t b0, uint32_t b1) {
    asm volatile("mma.sync.aligned.m16n8k16.row.col.f32.bf16.bf16.f32 "
                 "{%0,%1,%2,%3}, {%4,%5,%6,%7}, {%8,%9}, {%0,%1,%2,%3};"
                 : "+f"(c[0]), "+f"(c[1]), "+f"(c[2]), "+f"(c[3])
                 : "r"(a[0]), "r"(a[1]), "r"(a[2]), "r"(a[3]), "r"(b0), "r"(b1));
}
#define CP16(s, g) asm volatile("cp.async.cg.shared.global [%0], [%1], 16;" :: "r"(s), "l"(g))
#define CP4(s, g)  asm volatile("cp.async.ca.shared.global [%0], [%1], 4;"  :: "r"(s), "l"(g))
#define CPCOMMIT() asm volatile("cp.async.commit_group;" ::: "memory")
#define CPWAIT0()  asm volatile("cp.async.wait_group 0;" ::: "memory")

__device__ __forceinline__ uint32_t pack_bf16(float a, float b) {
    __nv_bfloat162 h = __floats2bfloat162_rn(a, b);
    return *reinterpret_cast<uint32_t*>(&h);
}
__device__ __forceinline__ void split2(float f, float& h, float& l) {
    __nv_bfloat16 hb = __float2bfloat16_rn(f);
    h = __bfloat162float(hb);
    l = f - h;
}
__device__ __forceinline__ bool better(float av, int ai, float bv, int bi) {
    return av < bv || (av == bv && ai < bi);
}
__device__ __forceinline__ void upd(float sc, int col, float& bv, int& bi, float& b2v, int& b2i) {
    if (sc < bv)        { b2v = bv; b2i = bi; bv = sc; bi = col; }
    else if (sc < b2v || (sc == b2v && col < b2i)) { b2v = sc; b2i = col; }
}
__device__ __forceinline__ void merge2(float& bv, int& bi, float& b2v, int& b2i,
                                       float ov, int oi, float o2v, int o2i) {
    if (better(ov, oi, bv, bi)) {
        float nv; int ni;
        if (better(bv, bi, o2v, o2i)) { nv = bv; ni = bi; } else { nv = o2v; ni = o2i; }
        bv = ov; bi = oi; b2v = nv; b2i = ni;
    } else if (better(ov, oi, b2v, b2i)) {
        b2v = ov; b2i = oi;
    }
}

// ======================= prologue: centers -> hi/lo bf16 + c2 =======================
__global__ void prep_centers(const float* __restrict__ c) {
    int warp = (blockIdx.x * blockDim.x + threadIdx.x) >> 5;
    int lane = threadIdx.x & 31;
    if (warp >= N_CENTERS) return;
    float4 v = reinterpret_cast<const float4*>(c + (size_t)warp * DIM)[lane];
    float s = v.x * v.x + v.y * v.y + v.z * v.z + v.w * v.w;
    float h0, l0, h1, l1, h2, l2, h3, l3;
    split2(v.x, h0, l0); split2(v.y, h1, l1); split2(v.z, h2, l2); split2(v.w, h3, l3);
    reinterpret_cast<uint2*>(g_ch + (size_t)warp * DIM)[lane] =
        make_uint2(pack_bf16(h0, h1), pack_bf16(h2, h3));
    reinterpret_cast<uint2*>(g_cl + (size_t)warp * DIM)[lane] =
        make_uint2(pack_bf16(l0, l1), pack_bf16(l2, l3));
    #pragma unroll
    for (int o = 16; o; o >>= 1) s += __shfl_xor_sync(0xffffffffu, s, o);
    if (lane == 0) g_c2[warp] = s;
}

// =============================== main kernel ===============================
__global__ __launch_bounds__(NTHREADS, 3)
void kmeans_hmma_kernel(const float* __restrict__ x, const float* __restrict__ cen,
                        float* __restrict__ out, int write_idx) {
    extern __shared__ char smem[];
    const uint32_t sbase = smem_u32(smem);
    const int tid  = threadIdx.x;
    const int warp = tid >> 5;
    const int lane = tid & 31;
    const int wr = warp & 1;      // row group: rows wr*32 .. +32
    const int wc = warp >> 1;     // col group: cols wc*16 .. +16
    const int sub = lane >> 3;
    const int i8  = lane & 7;
    const int row0 = blockIdx.x * BM;

    // ---- stage x rows into XH/XL (hi/lo bf16, swizzled) ----
    {
        int r = tid >> 2, h = tid & 3;   // thread covers elems [h*32, h*32+32)
        const float4* src = reinterpret_cast<const float4*>(
            x + (size_t)(row0 + r) * DIM + h * 32);
        #pragma unroll
        for (int j = 0; j < 4; j++) {
            float4 v0 = src[j * 2], v1 = src[j * 2 + 1];
            float h0,l0,h1,l1,h2,l2,h3,l3,h4,l4,h5,l5,h6,l6,h7,l7;
            split2(v0.x,h0,l0); split2(v0.y,h1,l1); split2(v0.z,h2,l2); split2(v0.w,h3,l3);
            split2(v1.x,h4,l4); split2(v1.y,h5,l5); split2(v1.z,h6,l6); split2(v1.w,h7,l7);
            uint32_t so = SWZ(r, h * 64 + j * 16);
            *reinterpret_cast<uint4*>(smem + SM_XH + so) =
                make_uint4(pack_bf16(h0,h1), pack_bf16(h2,h3), pack_bf16(h4,h5), pack_bf16(h6,h7));
            *reinterpret_cast<uint4*>(smem + SM_XL + so) =
                make_uint4(pack_bf16(l0,l1), pack_bf16(l2,l3), pack_bf16(l4,l5), pack_bf16(l6,l7));
        }
    }

    // ---- cp.async loader for a center chunk (CH + CL, single buffer) ----
    auto load_chunk = [&](int chunk, int c2buf) {
        const __nv_bfloat16* gh = g_ch + (size_t)chunk * NC * DIM;
        const __nv_bfloat16* gl = g_cl + (size_t)chunk * NC * DIM;
        #pragma unroll
        for (int it = 0; it < 4; it++) {
            int v = tid + it * NTHREADS;
            int r = v >> 4, c16 = v & 15;
            uint32_t so = SWZ(r, c16 * 16);
            CP16(sbase + SM_CH + so, gh + r * DIM + c16 * 8);
            CP16(sbase + SM_CL + so, gl + r * DIM + c16 * 8);
        }
        if (tid < NC)
            CP4(sbase + SM_C2 + c2buf * 256 + tid * 4, g_c2 + chunk * NC + tid);
    };

    load_chunk(0, 0);
    CPCOMMIT();
    CPWAIT0();
    __syncthreads();   // x tiles + chunk 0 visible

    // per-thread ldmatrix address components
    const uint32_t aRowB = (uint32_t)(wr * 32 + ((sub & 1) << 3) + i8) * 256;
    const uint32_t aKb   = (uint32_t)((sub >> 1) << 4);
    const uint32_t bRowB = (uint32_t)(wc * 16 + ((sub >> 1) << 3) + i8) * 256;
    const uint32_t bKb   = (uint32_t)((sub & 1) << 4);
    const uint32_t kXor  = (uint32_t)(i8 << 4);

    // top-2 state: 4 rows per thread
    float bv[4]  = {3.402823e38f, 3.402823e38f, 3.402823e38f, 3.402823e38f};
    float b2v[4] = {3.402823e38f, 3.402823e38f, 3.402823e38f, 3.402823e38f};
    int   bi[4]  = {0x7fffffff, 0x7fffffff, 0x7fffffff, 0x7fffffff};
    int   b2i[4] = {0x7fffffff, 0x7fffffff, 0x7fffffff, 0x7fffffff};

    #pragma unroll 1
    for (int ci = 0; ci < NCHUNK; ci++) {
        const int c2buf = ci & 1;

        float acc[2][2][4];
        #pragma unroll
        for (int mt = 0; mt < 2; mt++)
            #pragma unroll
            for (int nt = 0; nt < 2; nt++)
                #pragma unroll
                for (int q = 0; q < 4; q++) acc[mt][nt][q] = 0.f;

        #pragma unroll
        for (int ks = 0; ks < 8; ks++) {
            const uint32_t kb = ks * 32;
            const uint32_t aOff = aRowB + ((kb + aKb) ^ kXor);
            const uint32_t bOff = bRowB + ((kb + bKb) ^ kXor);
            uint32_t ah[8], al[8], bh[4], bl[4];
            ldsm4(ah[0], ah[1], ah[2], ah[3], sbase + SM_XH + aOff);
            ldsm4(ah[4], ah[5], ah[6], ah[7], sbase + SM_XH + aOff + 16 * 256);
            ldsm4(al[0], al[1], al[2], al[3], sbase + SM_XL + aOff);
            ldsm4(al[4], al[5], al[6], al[7], sbase + SM_XL + aOff + 16 * 256);
            ldsm4(bh[0], bh[1], bh[2], bh[3], sbase + SM_CH + bOff);
            ldsm4(bl[0], bl[1], bl[2], bl[3], sbase + SM_CL + bOff);
            // pass 1: XH * CH ; pass 2: XH * CL ; pass 3: XL * CH
            #pragma unroll
            for (int mt = 0; mt < 2; mt++)
                #pragma unroll
                for (int nt = 0; nt < 2; nt++)
                    mma16816(acc[mt][nt], &ah[mt*4], bh[nt*2], bh[nt*2 + 1]);
            #pragma unroll
            for (int mt = 0; mt < 2; mt++)
                #pragma unroll
                for (int nt = 0; nt < 2; nt++)
                    mma16816(acc[mt][nt], &ah[mt*4], bl[nt*2], bl[nt*2 + 1]);
            #pragma unroll
            for (int mt = 0; mt < 2; mt++)
                #pragma unroll
                for (int nt = 0; nt < 2; nt++)
                    mma16816(acc[mt][nt], &al[mt*4], bh[nt*2], bh[nt*2 + 1]);
        }

        __syncthreads();   // all warps done reading CH/CL
        // overwrite the single buffer with next chunk; flight overlaps epilogue
        if (ci + 1 < NCHUNK) {
            load_chunk(ci + 1, c2buf ^ 1);
            CPCOMMIT();
        }

        // epilogue: sc = c2 - 2*dot, running top-2 (c2 double-buffered)
        const float* c2s = reinterpret_cast<const float*>(smem + SM_C2 + c2buf * 256);
        float2 c2r[2];
        #pragma unroll
        for (int nt = 0; nt < 2; nt++)
            c2r[nt] = *reinterpret_cast<const float2*>(&c2s[wc * 16 + nt * 8 + 2 * (lane & 3)]);
        const int colBase = ci * NC + wc * 16 + 2 * (lane & 3);
        #pragma unroll
        for (int nt = 0; nt < 2; nt++) {
            const int col = colBase + nt * 8;
            #pragma unroll
            for (int mt = 0; mt < 2; mt++) {
                upd(fmaf(-2.f, acc[mt][nt][0], c2r[nt].x), col,     bv[mt*2],   bi[mt*2],   b2v[mt*2],   b2i[mt*2]);
                upd(fmaf(-2.f, acc[mt][nt][1], c2r[nt].y), col + 1, bv[mt*2],   bi[mt*2],   b2v[mt*2],   b2i[mt*2]);
                upd(fmaf(-2.f, acc[mt][nt][2], c2r[nt].x), col,     bv[mt*2+1], bi[mt*2+1], b2v[mt*2+1], b2i[mt*2+1]);
                upd(fmaf(-2.f, acc[mt][nt][3], c2r[nt].y), col + 1, bv[mt*2+1], bi[mt*2+1], b2v[mt*2+1], b2i[mt*2+1]);
            }
        }

        if (ci + 1 < NCHUNK) {
            CPWAIT0();
            __syncthreads();   // next chunk visible
        }
    }

    // ---- quad butterfly (lanes sharing the same rows) ----
    #pragma unroll
    for (int m = 1; m <= 2; m <<= 1) {
        #pragma unroll
        for (int rid = 0; rid < 4; rid++) {
            float ov  = __shfl_xor_sync(0xffffffffu, bv[rid],  m);
            int   oi  = __shfl_xor_sync(0xffffffffu, bi[rid],  m);
            float o2v = __shfl_xor_sync(0xffffffffu, b2v[rid], m);
            int   o2i = __shfl_xor_sync(0xffffffffu, b2i[rid], m);
            merge2(bv[rid], bi[rid], b2v[rid], b2i[rid], ov, oi, o2v, o2i);
        }
    }
    if ((lane & 3) == 0) {
        #pragma unroll
        for (int rid = 0; rid < 4; rid++) {
            int rl = wr * 32 + (rid >> 1) * 16 + (lane >> 2) + (rid & 1) * 8;
            *reinterpret_cast<float4*>(smem + SM_RED + (rl * 4 + wc) * 16) =
                make_float4(bv[rid], __int_as_float(bi[rid]), b2v[rid], __int_as_float(b2i[rid]));
        }
    }
    __syncthreads();

    // ---- final merge (4 col-warps) + exact fp32 top-2 refine ----
    if (tid < BM) {
        float4 e0 = *reinterpret_cast<float4*>(smem + SM_RED + (tid * 4 + 0) * 16);
        float fbv = e0.x; int fbi = __float_as_int(e0.y);
        float f2v = e0.z; int f2i = __float_as_int(e0.w);
        #pragma unroll
        for (int wcc = 1; wcc < 4; wcc++) {
            float4 e = *reinterpret_cast<float4*>(smem + SM_RED + (tid * 4 + wcc) * 16);
            merge2(fbv, fbi, f2v, f2i, e.x, __float_as_int(e.y), e.z, __float_as_int(e.w));
        }

        const int row = row0 + tid;
        const float4* xr = reinterpret_cast<const float4*>(x   + (size_t)row * DIM);
        const float4* c1 = reinterpret_cast<const float4*>(cen + (size_t)fbi * DIM);
        const float4* c2 = reinterpret_cast<const float4*>(cen + (size_t)f2i * DIM);
        float x2 = 0.f, d1 = 0.f, d2 = 0.f;
        #pragma unroll
        for (int k = 0; k < 32; k++) {
            float4 xv = xr[k], a = c1[k], b = c2[k];
            x2 = fmaf(xv.x, xv.x, x2); x2 = fmaf(xv.y, xv.y, x2);
            x2 = fmaf(xv.z, xv.z, x2); x2 = fmaf(xv.w, xv.w, x2);
            d1 = fmaf(xv.x, a.x, d1);  d1 = fmaf(xv.y, a.y, d1);
            d1 = fmaf(xv.z, a.z, d1);  d1 = fmaf(xv.w, a.w, d1);
            d2 = fmaf(xv.x, b.x, d2);  d2 = fmaf(xv.y, b.y, d2);
            d2 = fmaf(xv.z, b.z, d2);  d2 = fmaf(xv.w, b.w, d2);
        }
        float dist1 = fmaf(-2.f, d1, x2 + g_c2[fbi]);
        float dist2 = fmaf(-2.f, d2, x2 + g_c2[f2i]);
        float cost; int widx;
        if (better(dist2, f2i, dist1, fbi)) { cost = dist2; widx = f2i; }
        else                                 { cost = dist1; widx = fbi; }
        out[row] = cost > 0.f ? cost : 0.f;
        if (write_idx) out[N_POINTS + row] = (float)widx;
    }
}

// =============================== launch ===============================
extern "C" void kernel_launch(void* const* d_in, const int* in_sizes, int n_in,
                              void* d_out, int out_size) {
    const float* x = (const float*)d_in[0];   // [131072, 128]
    const float* c = (const float*)d_in[1];   // [1024, 128]
    float* out = (float*)d_out;

    prep_centers<<<N_CENTERS / 8, 256>>>(c);

    cudaFuncSetAttribute(kmeans_hmma_kernel,
                         cudaFuncAttributeMaxDynamicSharedMemorySize, SMEM_TOTAL);
    int write_idx = (out_size >= 2 * N_POINTS) ? 1 : 0;
    kmeans_hmma_kernel<<<N_POINTS / BM, NTHREADS, SMEM_TOTAL>>>(x, c, out, write_idx);
}